// round 10
// baseline (speedup 1.0000x reference)
#include <cuda_runtime.h>
#include <cuda_bf16.h>
#include <math.h>
#include <stdint.h>

#define B_   4
#define S_   2048
#define E_   1024
#define H_   16
#define DH_  64
#define BH_  (B_*H_)
#define M_   (B_*S_)
#define PA   40      // smem pitch (bf16) KC=32 tiles (80B rows)
#define PS   72      // smem pitch (bf16) KC=64 tiles (144B rows)
#define PV   72      // smem pitch (bf16) 32x64 V tiles

// ---- smem geometry ----
#define TQA (256*PA*2)            // 20480 A tile (256x32)
#define TQB (128*PA*2)            // 10240 B tile (128x32)
#define QBUF (2*TQA+2*TQB)        // 61440 per buffer {Ah,Al,Bh,Bl}
#define DSM_Q 135168              // max(2*QBUF, 256*132*4 epilogue)
#define TSA (256*PS*2)            // 36864
#define TSB (128*PS*2)            // 18432
#define DSM_S (2*TSA+2*TSB)       // 110592
#define TPP (256*PA*2)            // 20480 P tile
#define TPV (32*PV*2)             // 4608  V tile
#define PVBUF (2*TPP+2*TPV)       // 50176
#define DSM_P (2*PVBUF)           // 100352
#define EPIT 132                  // fp32 epilogue pitch

// ---- device scratch (allocation-free) ----
__device__ __nv_bfloat16 g_Xh[(size_t)3*M_*E_], g_Xl[(size_t)3*M_*E_];   // pre-split q,k,v
__device__ __nv_bfloat16 g_Wh[(size_t)4*E_*E_], g_Wl[(size_t)4*E_*E_];   // wq,wk,wv,wo
__device__ __nv_bfloat16 g_Qh[BH_*S_*DH_], g_Ql[BH_*S_*DH_];
__device__ __nv_bfloat16 g_Kh[BH_*S_*DH_], g_Kl[BH_*S_*DH_];
__device__ __nv_bfloat16 g_Vh[BH_*S_*DH_], g_Vl[BH_*S_*DH_];
__device__ __nv_bfloat16 g_Ch[(size_t)M_*E_], g_Cl[(size_t)M_*E_];

static __device__ __forceinline__ uint32_t s2u(const void* p) {
    return (uint32_t)__cvta_generic_to_shared(p);
}
static __device__ __forceinline__ void cpa16(uint32_t d, const void* s) {
    asm volatile("cp.async.cg.shared.global [%0], [%1], 16;" :: "r"(d), "l"(s));
}
static __device__ __forceinline__ void cpa_commit() {
    asm volatile("cp.async.commit_group;");
}
template<int N> static __device__ __forceinline__ void cpa_wait() {
    asm volatile("cp.async.wait_group %0;" :: "n"(N));
}
static __device__ __forceinline__ void ldsm4(uint32_t* r, uint32_t a) {
    asm volatile("ldmatrix.sync.aligned.m8n8.x4.shared.b16 {%0,%1,%2,%3}, [%4];\n"
        : "=r"(r[0]), "=r"(r[1]), "=r"(r[2]), "=r"(r[3]) : "r"(a));
}
static __device__ __forceinline__ void ldsm4t(uint32_t* r, uint32_t a) {
    asm volatile("ldmatrix.sync.aligned.m8n8.x4.trans.shared.b16 {%0,%1,%2,%3}, [%4];\n"
        : "=r"(r[0]), "=r"(r[1]), "=r"(r[2]), "=r"(r[3]) : "r"(a));
}
static __device__ __forceinline__ void mma16816(float* c, const uint32_t* a, const uint32_t* b) {
    asm("mma.sync.aligned.m16n8k16.row.col.f32.bf16.bf16.f32 "
        "{%0,%1,%2,%3}, {%4,%5,%6,%7}, {%8,%9}, {%0,%1,%2,%3};\n"
        : "+f"(c[0]), "+f"(c[1]), "+f"(c[2]), "+f"(c[3])
        : "r"(a[0]), "r"(a[1]), "r"(a[2]), "r"(a[3]), "r"(b[0]), "r"(b[1]));
}
static __device__ __forceinline__ void split2(float a, float b, uint32_t& hi, uint32_t& lo) {
    __nv_bfloat16 ha = __float2bfloat16(a), hb = __float2bfloat16(b);
    __nv_bfloat16 la = __float2bfloat16(a - __bfloat162float(ha));
    __nv_bfloat16 lb = __float2bfloat16(b - __bfloat162float(hb));
    __nv_bfloat162 Hh; Hh.x = ha; Hh.y = hb; hi = *(uint32_t*)&Hh;
    __nv_bfloat162 Ll; Ll.x = la; Ll.y = lb; lo = *(uint32_t*)&Ll;
}
static __device__ __forceinline__ void split8(const float4& x0, const float4& x1,
                                              uint4& H, uint4& L) {
    split2(x0.x, x0.y, H.x, L.x);
    split2(x0.z, x0.w, H.y, L.y);
    split2(x1.x, x1.y, H.z, L.z);
    split2(x1.z, x1.w, H.w, L.w);
}

// 64x64 warp tile over a staged chunk. acc[4 mf][8 nf][4].
template<int PITCH, int KSTEPS>
static __device__ __forceinline__ void compute64(
    const __nv_bfloat16* Ah, const __nv_bfloat16* Al,
    const __nv_bfloat16* Bh, const __nv_bfloat16* Bl,
    float (&acc)[4][8][4], int wm, int wn, int lane)
{
    const int arow = wm * 64 + (lane & 15);
    const int brow = wn * 64 + (lane & 7) + ((lane & 16) ? 8 : 0);
#pragma unroll
    for (int s = 0; s < KSTEPS; s++) {
        const int ak = s * 16 + ((lane & 16) ? 8 : 0);
        const int bk = s * 16 + ((lane & 8) ? 8 : 0);
        uint32_t ah[4][4], al[4][4];
#pragma unroll
        for (int mf = 0; mf < 4; mf++) {
            ldsm4(ah[mf], s2u(&Ah[(arow + 16 * mf) * PITCH + ak]));
            ldsm4(al[mf], s2u(&Al[(arow + 16 * mf) * PITCH + ak]));
        }
#pragma unroll
        for (int j = 0; j < 4; j++) {
            uint32_t th[4], tl[4];
            ldsm4(th, s2u(&Bh[(brow + 16 * j) * PITCH + bk]));
            ldsm4(tl, s2u(&Bl[(brow + 16 * j) * PITCH + bk]));
#pragma unroll
            for (int mf = 0; mf < 4; mf++) {
                mma16816(acc[mf][2*j],   ah[mf], th);
                mma16816(acc[mf][2*j+1], ah[mf], th + 2);
                mma16816(acc[mf][2*j],   al[mf], th);
                mma16816(acc[mf][2*j+1], al[mf], th + 2);
                mma16816(acc[mf][2*j],   ah[mf], tl);
                mma16816(acc[mf][2*j+1], ah[mf], tl + 2);
            }
        }
    }
}

// ---------------------------------------------------------------------------
// Kernel 0: pre-split q,k,v and the 4 weights into bf16 hi/lo. grid(4096,7).
// ---------------------------------------------------------------------------
__global__ __launch_bounds__(256) void k_presplit(
    const float* __restrict__ q, const float* __restrict__ k, const float* __restrict__ v,
    const float* __restrict__ wq, const float* __restrict__ wk,
    const float* __restrict__ wv, const float* __restrict__ wo)
{
    const int z = blockIdx.y;
    const float* src;
    __nv_bfloat16 *dh, *dl;
    size_t n;
    if (z < 3) {
        src = (z == 0) ? q : (z == 1) ? k : v;
        dh = g_Xh + (size_t)z * M_ * E_;
        dl = g_Xl + (size_t)z * M_ * E_;
        n = (size_t)M_ * E_;
    } else {
        int w = z - 3;
        src = (w == 0) ? wq : (w == 1) ? wk : (w == 2) ? wv : wo;
        dh = g_Wh + (size_t)w * E_ * E_;
        dl = g_Wl + (size_t)w * E_ * E_;
        n = (size_t)E_ * E_;
    }
    size_t base = ((size_t)blockIdx.x * 256 + threadIdx.x) * 8;
    if (base >= n) return;
    float4 x0 = *(const float4*)&src[base];
    float4 x1 = *(const float4*)&src[base + 4];
    uint4 H, L;
    split8(x0, x1, H, L);
    *(uint4*)&dh[base] = H;
    *(uint4*)&dl[base] = L;
}

// ---------------------------------------------------------------------------
// Kernel 1: QKV projections. block 256x128, 256 thr, cp.async pipelined.
// ---------------------------------------------------------------------------
__global__ __launch_bounds__(256) void k_qkv(
    const float* __restrict__ bq, const float* __restrict__ bk, const float* __restrict__ bv)
{
    extern __shared__ char dsm[];
    const int z = blockIdx.z;
    const __nv_bfloat16* Xh = g_Xh + (size_t)z * M_ * E_;
    const __nv_bfloat16* Xl = g_Xl + (size_t)z * M_ * E_;
    const __nv_bfloat16* Wh = g_Wh + (size_t)z * E_ * E_;
    const __nv_bfloat16* Wl = g_Wl + (size_t)z * E_ * E_;
    const float* bias = (z == 0) ? bq : (z == 1) ? bk : bv;
    __nv_bfloat16* dsth = (z == 0) ? g_Qh : (z == 1) ? g_Kh : g_Vh;
    __nv_bfloat16* dstl = (z == 0) ? g_Ql : (z == 1) ? g_Kl : g_Vl;

    const int tid = threadIdx.x, wid = tid >> 5, lane = tid & 31;
    const int wm = wid >> 1, wn = wid & 1;
    const int row0 = blockIdx.x * 256, col0 = blockIdx.y * 128;

    auto stage = [&](int buf, int kt) {
        uint32_t sb = s2u(dsm) + buf * QBUF;
#pragma unroll
        for (int i = 0; i < 4; i++) {
            int ch = tid + i * 256;
            int r = ch >> 2, c = ch & 3;
            uint32_t d = sb + r * (PA * 2) + c * 16;
            size_t so = (size_t)(row0 + r) * E_ + kt + c * 8;
            cpa16(d, Xh + so);
            cpa16(d + TQA, Xl + so);
        }
#pragma unroll
        for (int i = 0; i < 2; i++) {
            int ch = tid + i * 256;
            int r = ch >> 2, c = ch & 3;
            uint32_t d = sb + 2 * TQA + r * (PA * 2) + c * 16;
            size_t so = (size_t)(col0 + r) * E_ + kt + c * 8;
            cpa16(d, Wh + so);
            cpa16(d + TQB, Wl + so);
        }
    };

    float acc[4][8][4];
#pragma unroll
    for (int a = 0; a < 4; a++)
#pragma unroll
        for (int bn = 0; bn < 8; bn++)
#pragma unroll
            for (int e = 0; e < 4; e++) acc[a][bn][e] = 0.f;

    stage(0, 0); cpa_commit();
    cpa_wait<0>(); __syncthreads();

    const int NCH = E_ / 32;
    for (int c = 0; c < NCH; c++) {
        if (c + 1 < NCH) { stage((c + 1) & 1, (c + 1) * 32); cpa_commit(); }
        char* bb = dsm + (c & 1) * QBUF;
        compute64<PA, 2>((__nv_bfloat16*)bb, (__nv_bfloat16*)(bb + TQA),
                         (__nv_bfloat16*)(bb + 2 * TQA), (__nv_bfloat16*)(bb + 2 * TQA + TQB),
                         acc, wm, wn, lane);
        if (c + 1 < NCH) { cpa_wait<0>(); __syncthreads(); }
    }
    __syncthreads();

    // epilogue via smem fp32
    float* st = (float*)dsm;
    const int g = lane >> 2, c2 = (lane & 3) * 2;
#pragma unroll
    for (int mf = 0; mf < 4; mf++)
#pragma unroll
        for (int nf = 0; nf < 8; nf++) {
            int row = wm * 64 + mf * 16 + g, col = wn * 64 + nf * 8 + c2;
            *(float2*)&st[row * EPIT + col] = make_float2(acc[mf][nf][0], acc[mf][nf][1]);
            *(float2*)&st[(row + 8) * EPIT + col] = make_float2(acc[mf][nf][2], acc[mf][nf][3]);
        }
    __syncthreads();
#pragma unroll
    for (int i = 0; i < 16; i++) {
        int idx = tid + i * 256;          // 4096 groups of 8 cols
        int g8 = idx & 15, m = idx >> 4;
        int cbase = g8 * 8;
        float4 x0 = *(float4*)&st[m * EPIT + cbase];
        float4 x1 = *(float4*)&st[m * EPIT + cbase + 4];
        int n0 = col0 + cbase;
        x0.x += __ldg(&bias[n0]);     x0.y += __ldg(&bias[n0 + 1]);
        x0.z += __ldg(&bias[n0 + 2]); x0.w += __ldg(&bias[n0 + 3]);
        x1.x += __ldg(&bias[n0 + 4]); x1.y += __ldg(&bias[n0 + 5]);
        x1.z += __ldg(&bias[n0 + 6]); x1.w += __ldg(&bias[n0 + 7]);
        uint4 Hv, Lv;
        split8(x0, x1, Hv, Lv);
        int mm = row0 + m;
        int b = mm >> 11, s = mm & (S_ - 1);
        int hd = n0 >> 6, d = n0 & 63;
        size_t o = (((size_t)(b * H_ + hd)) * S_ + s) * DH_ + d;
        *(uint4*)&dsth[o] = Hv;
        *(uint4*)&dstl[o] = Lv;
    }
}

// ---------------------------------------------------------------------------
// Kernel 2: scores = Q K^T / 8, causal. block 256x128. grid(8,16,64).
// ---------------------------------------------------------------------------
__global__ __launch_bounds__(256) void k_scores(float* __restrict__ attn)
{
    extern __shared__ char dsm[];
    const int qt = blockIdx.x, kt = blockIdx.y, bhd = blockIdx.z;
    const int row0 = qt * 256, col0 = kt * 128;
    float* A = attn + (size_t)bhd * S_ * S_;
    const int tid = threadIdx.x;

    if (col0 >= row0 + 256) {            // fully masked (different 128-col group): final 0
        float4 z = make_float4(0.f, 0.f, 0.f, 0.f);
#pragma unroll
        for (int i = 0; i < 32; i++) {
            int idx = tid + i * 256;
            int r = idx >> 5, c4 = (idx & 31) * 4;
            *(float4*)&A[(size_t)(row0 + r) * S_ + col0 + c4] = z;
        }
        return;
    }

    const __nv_bfloat16* Qh = g_Qh + (size_t)bhd * S_ * DH_;
    const __nv_bfloat16* Ql = g_Ql + (size_t)bhd * S_ * DH_;
    const __nv_bfloat16* Kh = g_Kh + (size_t)bhd * S_ * DH_;
    const __nv_bfloat16* Kl = g_Kl + (size_t)bhd * S_ * DH_;
    const int wid = tid >> 5, lane = tid & 31;
    const int wm = wid >> 1, wn = wid & 1;

    {   // single-shot staging of Q(256x64) and K(128x64) hi/lo
        uint32_t sb = s2u(dsm);
#pragma unroll
        for (int i = 0; i < 8; i++) {
            int ch = tid + i * 256;
            int r = ch >> 3, c = ch & 7;
            uint32_t d = sb + r * (PS * 2) + c * 16;
            size_t so = (size_t)(row0 + r) * DH_ + c * 8;
            cpa16(d, Qh + so);
            cpa16(d + TSA, Ql + so);
        }
#pragma unroll
        for (int i = 0; i < 4; i++) {
            int ch = tid + i * 256;
            int r = ch >> 3, c = ch & 7;
            uint32_t d = sb + 2 * TSA + r * (PS * 2) + c * 16;
            size_t so = (size_t)(col0 + r) * DH_ + c * 8;
            cpa16(d, Kh + so);
            cpa16(d + TSB, Kl + so);
        }
        cpa_commit();
    }
    cpa_wait<0>(); __syncthreads();

    float acc[4][8][4];
#pragma unroll
    for (int a = 0; a < 4; a++)
#pragma unroll
        for (int bn = 0; bn < 8; bn++)
#pragma unroll
            for (int e = 0; e < 4; e++) acc[a][bn][e] = 0.f;

    compute64<PS, 4>((__nv_bfloat16*)dsm, (__nv_bfloat16*)(dsm + TSA),
                     (__nv_bfloat16*)(dsm + 2 * TSA), (__nv_bfloat16*)(dsm + 2 * TSA + TSB),
                     acc, wm, wn, lane);

    const int g = lane >> 2, c2 = (lane & 3) * 2;
#pragma unroll
    for (int mf = 0; mf < 4; mf++)
#pragma unroll
        for (int nf = 0; nf < 8; nf++)
#pragma unroll
            for (int eh = 0; eh < 2; eh++) {
                int gi = row0 + wm * 64 + mf * 16 + g + eh * 8;
                int gj = col0 + wn * 64 + nf * 8 + c2;
                // masked: -1e30 within gi's own 128-col group (softmax will zero it),
                // 0 beyond (softmax never touches it; 0 is the final attn value).
                float v0, v1;
                float m0 = ((gj >> 7) == (gi >> 7)) ? -1e30f : 0.0f;
                float m1 = (((gj + 1) >> 7) == (gi >> 7)) ? -1e30f : 0.0f;
                v0 = (gj <= gi) ? acc[mf][nf][eh * 2] * 0.125f : m0;
                v1 = (gj + 1 <= gi) ? acc[mf][nf][eh * 2 + 1] * 0.125f : m1;
                *(float2*)&A[(size_t)gi * S_ + gj] = make_float2(v0, v1);
            }
}

// ---------------------------------------------------------------------------
// Kernel 3: causal-aware row softmax in place. One block per row.
// ---------------------------------------------------------------------------
__global__ __launch_bounds__(256) void k_softmax(float* __restrict__ attn)
{
    const int s = blockIdx.x & (S_ - 1);
    const int ncols4 = ((s >> 7) + 1) * 32;
    float4* p = (float4*)(attn + (size_t)blockIdx.x * S_);
    const int t = threadIdx.x;
    __shared__ float red[256];

    float4 a0 = make_float4(-1e30f, -1e30f, -1e30f, -1e30f);
    float4 a1 = a0;
    const bool v0 = t < ncols4, v1 = (t + 256) < ncols4;
    if (v0) a0 = p[t];
    if (v1) a1 = p[t + 256];

    float m = fmaxf(fmaxf(fmaxf(a0.x, a0.y), fmaxf(a0.z, a0.w)),
                    fmaxf(fmaxf(a1.x, a1.y), fmaxf(a1.z, a1.w)));
    red[t] = m; __syncthreads();
    for (int st = 128; st > 0; st >>= 1) {
        if (t < st) red[t] = fmaxf(red[t], red[t + st]);
        __syncthreads();
    }
    m = red[0]; __syncthreads();

    a0.x = __expf(a0.x - m); a0.y = __expf(a0.y - m);
    a0.z = __expf(a0.z - m); a0.w = __expf(a0.w - m);
    a1.x = __expf(a1.x - m); a1.y = __expf(a1.y - m);
    a1.z = __expf(a1.z - m); a1.w = __expf(a1.w - m);
    float sum = 0.f;
    if (v0) sum += a0.x + a0.y + a0.z + a0.w;
    if (v1) sum += a1.x + a1.y + a1.z + a1.w;
    red[t] = sum; __syncthreads();
    for (int st = 128; st > 0; st >>= 1) {
        if (t < st) red[t] += red[t + st];
        __syncthreads();
    }
    const float inv = 1.f / red[0];

    a0.x *= inv; a0.y *= inv; a0.z *= inv; a0.w *= inv;
    a1.x *= inv; a1.y *= inv; a1.z *= inv; a1.w *= inv;
    if (v0) p[t] = a0;
    if (v1) p[t + 256] = a1;
}

// ---------------------------------------------------------------------------
// Kernel 4: context = attn @ V. block 256x64, warp 64x32, grid(8,1,64).
// ---------------------------------------------------------------------------
__global__ __launch_bounds__(256) void k_pv(const float* __restrict__ attn)
{
    extern __shared__ char dsm[];
    const int qt = blockIdx.x, bhd = blockIdx.z;
    const int row0 = qt * 256;
    const float* P = attn + (size_t)bhd * S_ * S_;
    const __nv_bfloat16* Vh = g_Vh + (size_t)bhd * S_ * DH_;
    const __nv_bfloat16* Vl = g_Vl + (size_t)bhd * S_ * DH_;
    const int b = bhd >> 4, hd = bhd & 15;

    const int tid = threadIdx.x, wid = tid >> 5, lane = tid & 31;
    const int wm = wid >> 1, wn = wid & 1;

    // P register staging: 8 rows/warp-lane pattern (coalesced 128B row segments)
    const int pr = tid >> 3, pc4 = (tid & 7) * 4;
    float4 rp[8];
    auto loadP = [&](int kt) {
#pragma unroll
        for (int i = 0; i < 8; i++)
            rp[i] = *(const float4*)&P[(size_t)(row0 + pr + i * 32) * S_ + kt + pc4];
    };
    auto storeP = [&](int buf) {
        char* pb = dsm + buf * PVBUF;
#pragma unroll
        for (int i = 0; i < 8; i++) {
            uint32_t h0, l0, h1, l1;
            split2(rp[i].x, rp[i].y, h0, l0);
            split2(rp[i].z, rp[i].w, h1, l1);
            int off = ((pr + i * 32) * PA + pc4) * 2;
            *(uint2*)(pb + off) = make_uint2(h0, h1);
            *(uint2*)(pb + TPP + off) = make_uint2(l0, l1);
        }
    };
    auto stageV = [&](int buf, int kt) {
        uint32_t vb = s2u(dsm) + buf * PVBUF + 2 * TPP;
        int r = tid >> 3, c = tid & 7;
        uint32_t d = vb + r * (PV * 2) + c * 16;
        size_t so = (size_t)(kt + r) * DH_ + c * 8;
        cpa16(d, Vh + so);
        cpa16(d + TPV, Vl + so);
    };

    float acc[4][4][4];
#pragma unroll
    for (int a = 0; a < 4; a++)
#pragma unroll
        for (int bn = 0; bn < 4; bn++)
#pragma unroll
            for (int e = 0; e < 4; e++) acc[a][bn][e] = 0.f;

    loadP(0); storeP(0); stageV(0, 0); cpa_commit();
    cpa_wait<0>(); __syncthreads();

    const int NCH = (row0 + 256) / 32;       // causal bound
    const int arow = wm * 64 + (lane & 15);
    const int vcol = wn * 32 + ((lane & 16) ? 8 : 0);
    for (int c = 0; c < NCH; c++) {
        if (c + 1 < NCH) { loadP((c + 1) * 32); stageV((c + 1) & 1, (c + 1) * 32); cpa_commit(); }
        char* pb = dsm + (c & 1) * PVBUF;
        const __nv_bfloat16* Ph = (__nv_bfloat16*)pb;
        const __nv_bfloat16* Pl = (__nv_bfloat16*)(pb + TPP);
        const __nv_bfloat16* Vsh = (__nv_bfloat16*)(pb + 2 * TPP);
        const __nv_bfloat16* Vsl = (__nv_bfloat16*)(pb + 2 * TPP + TPV);
#pragma unroll
        for (int ks = 0; ks < 32; ks += 16) {
            const int ak = ks + ((lane & 16) ? 8 : 0);
            const int vrow = ks + (lane & 7) + ((lane & 8) ? 8 : 0);
            uint32_t ah[4][4], al[4][4];
#pragma unroll
            for (int mf = 0; mf < 4; mf++) {
                ldsm4(ah[mf], s2u(&Ph[(arow + 16 * mf) * PA + ak]));
                ldsm4(al[mf], s2u(&Pl[(arow + 16 * mf) * PA + ak]));
            }
#pragma unroll
            for (int j = 0; j < 2; j++) {
                uint32_t th[4], tl[4];
                ldsm4t(th, s2u(&Vsh[vrow * PV + vcol + 16 * j]));
                ldsm4t(tl, s2u(&Vsl[vrow * PV + vcol + 16 * j]));
#pragma unroll
                for (int mf = 0; mf < 4; mf++) {
                    mma16816(acc[mf][2*j],   ah[mf], th);
                    mma16816(acc[mf][2*j+1], ah[mf], th + 2);
                    mma16816(acc[mf][2*j],   al[mf], th);
                    mma16816(acc[mf][2*j+1], al[mf], th + 2);
                    mma16816(acc[mf][2*j],   ah[mf], tl);
                    mma16816(acc[mf][2*j+1], ah[mf], tl + 2);
                }
            }
        }
        if (c + 1 < NCH) { storeP((c + 1) & 1); cpa_wait<0>(); __syncthreads(); }
    }

    const int g = lane >> 2, c2 = (lane & 3) * 2;
#pragma unroll
    for (int mf = 0; mf < 4; mf++)
#pragma unroll
        for (int nf = 0; nf < 4; nf++) {
            int row = row0 + wm * 64 + mf * 16 + g;
            int col = wn * 32 + nf * 8 + c2;
            size_t o = ((size_t)(b * S_ + row)) * E_ + hd * DH_ + col;
            uint32_t h, l;
            split2(acc[mf][nf][0], acc[mf][nf][1], h, l);
            *(uint32_t*)&g_Ch[o] = h; *(uint32_t*)&g_Cl[o] = l;
            split2(acc[mf][nf][2], acc[mf][nf][3], h, l);
            *(uint32_t*)&g_Ch[o + 8 * E_] = h; *(uint32_t*)&g_Cl[o + 8 * E_] = l;
        }
}

// ---------------------------------------------------------------------------
// Kernel 5: out = Ctx @ wo^T + bo. Same skeleton as k_qkv. grid(32,8).
// ---------------------------------------------------------------------------
__global__ __launch_bounds__(256) void k_oproj(
    const float* __restrict__ bo, float* __restrict__ out)
{
    extern __shared__ char dsm[];
    const __nv_bfloat16* Wh = g_Wh + (size_t)3 * E_ * E_;
    const __nv_bfloat16* Wl = g_Wl + (size_t)3 * E_ * E_;

    const int tid = threadIdx.x, wid = tid >> 5, lane = tid & 31;
    const int wm = wid >> 1, wn = wid & 1;
    const int row0 = blockIdx.x * 256, col0 = blockIdx.y * 128;

    auto stage = [&](int buf, int kt) {
        uint32_t sb = s2u(dsm) + buf * QBUF;
#pragma unroll
        for (int i = 0; i < 4; i++) {
            int ch = tid + i * 256;
            int r = ch >> 2, c = ch & 3;
            uint32_t d = sb + r * (PA * 2) + c * 16;
            size_t so = (size_t)(row0 + r) * E_ + kt + c * 8;
            cpa16(d, g_Ch + so);
            cpa16(d + TQA, g_Cl + so);
        }
#pragma unroll
        for (int i = 0; i < 2; i++) {
            int ch = tid + i * 256;
            int r = ch >> 2, c = ch & 3;
            uint32_t d = sb + 2 * TQA + r * (PA * 2) + c * 16;
            size_t so = (size_t)(col0 + r) * E_ + kt + c * 8;
            cpa16(d, Wh + so);
            cpa16(d + TQB, Wl + so);
        }
    };

    float acc[4][8][4];
#pragma unroll
    for (int a = 0; a < 4; a++)
#pragma unroll
        for (int bn = 0; bn < 8; bn++)
#pragma unroll
            for (int e = 0; e < 4; e++) acc[a][bn][e] = 0.f;

    stage(0, 0); cpa_commit();
    cpa_wait<0>(); __syncthreads();

    const int NCH = E_ / 32;
    for (int c = 0; c < NCH; c++) {
        if (c + 1 < NCH) { stage((c + 1) & 1, (c + 1) * 32); cpa_commit(); }
        char* bb = dsm + (c & 1) * QBUF;
        compute64<PA, 2>((__nv_bfloat16*)bb, (__nv_bfloat16*)(bb + TQA),
                         (__nv_bfloat16*)(bb + 2 * TQA), (__nv_bfloat16*)(bb + 2 * TQA + TQB),
                         acc, wm, wn, lane);
        if (c + 1 < NCH) { cpa_wait<0>(); __syncthreads(); }
    }
    __syncthreads();

    float* st = (float*)dsm;
    const int g = lane >> 2, c2 = (lane & 3) * 2;
#pragma unroll
    for (int mf = 0; mf < 4; mf++)
#pragma unroll
        for (int nf = 0; nf < 8; nf++) {
            int row = wm * 64 + mf * 16 + g, col = wn * 64 + nf * 8 + c2;
            *(float2*)&st[row * EPIT + col] = make_float2(acc[mf][nf][0], acc[mf][nf][1]);
            *(float2*)&st[(row + 8) * EPIT + col] = make_float2(acc[mf][nf][2], acc[mf][nf][3]);
        }
    __syncthreads();
#pragma unroll
    for (int i = 0; i < 32; i++) {
        int idx = tid + i * 256;                 // 8192 float4 groups
        int c4 = idx & 31, m = idx >> 5;
        float4 x = *(float4*)&st[m * EPIT + c4 * 4];
        int n0 = col0 + c4 * 4;
        x.x += __ldg(&bo[n0]);     x.y += __ldg(&bo[n0 + 1]);
        x.z += __ldg(&bo[n0 + 2]); x.w += __ldg(&bo[n0 + 3]);
        *(float4*)&out[(size_t)(row0 + m) * E_ + n0] = x;
    }
}

// ---------------------------------------------------------------------------
extern "C" void kernel_launch(void* const* d_in, const int* in_sizes, int n_in,
                              void* d_out, int out_size)
{
    const float* q  = (const float*)d_in[0];
    const float* k  = (const float*)d_in[1];
    const float* v  = (const float*)d_in[2];
    const float* wq = (const float*)d_in[3];
    const float* bq = (const float*)d_in[4];
    const float* wk = (const float*)d_in[5];
    const float* bk = (const float*)d_in[6];
    const float* wv = (const float*)d_in[7];
    const float* bv = (const float*)d_in[8];
    const float* wo = (const float*)d_in[9];
    const float* bo = (const float*)d_in[10];

    float* out  = (float*)d_out;                       // [B,S,E]
    float* attn = out + (size_t)B_ * S_ * E_;          // [B,H,S,S]

    cudaFuncSetAttribute(k_qkv,    cudaFuncAttributeMaxDynamicSharedMemorySize, DSM_Q);
    cudaFuncSetAttribute(k_scores, cudaFuncAttributeMaxDynamicSharedMemorySize, DSM_S);
    cudaFuncSetAttribute(k_pv,     cudaFuncAttributeMaxDynamicSharedMemorySize, DSM_P);
    cudaFuncSetAttribute(k_oproj,  cudaFuncAttributeMaxDynamicSharedMemorySize, DSM_Q);

    k_presplit<<<dim3(4096, 7), 256>>>(q, k, v, wq, wk, wv, wo);
    k_qkv    <<<dim3(M_/256, E_/128, 3), 256, DSM_Q>>>(bq, bk, bv);
    k_scores <<<dim3(S_/256, S_/128, BH_), 256, DSM_S>>>(attn);
    k_softmax<<<dim3(BH_*S_), 256>>>(attn);
    k_pv     <<<dim3(S_/256, 1, BH_), 256, DSM_P>>>(attn);
    k_oproj  <<<dim3(M_/256, E_/128), 256, DSM_Q>>>(bo, out);
}